// round 7
// baseline (speedup 1.0000x reference)
#include <cuda_runtime.h>

#define BH_ 16

// 16B-aligned gmem scratch (float4-typed so staging can use LDG.128)
__device__ float4 g_xs4[BH_ * 1024];        // softmaxed x, stride 32 floats
__device__ float4 g_sv4[BH_ * 1056];        // sorted values, stride 33 floats
__device__ float4 g_q4 [BH_ * 128 * 33];    // rank table: (qA, qB, qC, r)
__device__ float4 g_o4 [BH_ * 1024];        // attn @ x, stride 32 floats

static const int SMEM_GEMM = 16 * 256 * 4 + 32 * 65 * 16;                 // 49664
static const int SMEM_SPL  = 128 * 33 * 16 + 128 * 33 * 4
                           + 128 * 32 * 4 + 16 * 128 * 4;                 // 109056

__device__ __forceinline__ float wmax(float v) {
    #pragma unroll
    for (int o = 16; o > 0; o >>= 1) v = fmaxf(v, __shfl_xor_sync(0xffffffffu, v, o));
    return v;
}
__device__ __forceinline__ float wsum(float v) {
    #pragma unroll
    for (int o = 16; o > 0; o >>= 1) v += __shfl_xor_sync(0xffffffffu, v, o);
    return v;
}
__device__ __forceinline__ float bitonic32(float v, int l) {
    #pragma unroll
    for (int k = 2; k <= 32; k <<= 1) {
        #pragma unroll
        for (int j = k >> 1; j > 0; j >>= 1) {
            const float o = __shfl_xor_sync(0xffffffffu, v, j);
            const bool up = ((l & k) == 0);
            const bool lower = ((l & j) == 0);
            v = (lower == up) ? fminf(v, o) : fmaxf(v, o);
        }
    }
    return v;
}
__device__ __forceinline__ float iscan2(float x, int l) {
    #pragma unroll
    for (int o = 1; o < 32; o <<= 1) {
        const float n = __shfl_up_sync(0xffffffffu, x, o);
        if (l >= o) x += n;
    }
    return x;
}

// ---------------------------------------------------------------------------
// K1: in-proj GEMM. 16 rows x 32 cols per block; warp = 2 rows, lane = col,
// full K in-warp (no cross-warp reduce). grid(16, 8), 256 thr.
// ---------------------------------------------------------------------------
__global__ void k_proj(const float* __restrict__ inp,
                       const float* __restrict__ w_in,
                       const float* __restrict__ b_in) {
    extern __shared__ float sm[];
    float*  xs = sm;                        // [16][256]
    float4* ws = (float4*)(sm + 16 * 256);  // [32][65]

    const int t = threadIdx.x, lane = t & 31, wid = t >> 5;
    const int r0 = blockIdx.x * 16, hd = blockIdx.y, c0 = hd * 32;

    #pragma unroll
    for (int f = t; f < 1024; f += 256) {
        const int r = f >> 6, kq = f & 63;
        *(float4*)(xs + r * 256 + kq * 4) = *(const float4*)(inp + (r0 + r) * 256 + kq * 4);
    }
    #pragma unroll
    for (int rr = 0; rr < 4; ++rr) {
        const int cc = wid * 4 + rr;
        #pragma unroll
        for (int hh = 0; hh < 2; ++hh) {
            const int k4 = hh * 32 + lane;
            ws[cc * 65 + k4] = *(const float4*)(w_in + (c0 + cc) * 256 + k4 * 4);
        }
    }
    __syncthreads();

    const float4* wrow = ws + lane * 65;
    const float* x0 = xs + (wid * 2 + 0) * 256;
    const float* x1 = xs + (wid * 2 + 1) * 256;
    float acc00 = 0.f, acc01 = 0.f, acc10 = 0.f, acc11 = 0.f;
    #pragma unroll 8
    for (int kq = 0; kq < 64; kq += 2) {
        const float4 wA = wrow[kq], wB = wrow[kq + 1];
        const float4 xa0 = *(const float4*)(x0 + 4 * kq);
        const float4 xa1 = *(const float4*)(x0 + 4 * kq + 4);
        const float4 xb0 = *(const float4*)(x1 + 4 * kq);
        const float4 xb1 = *(const float4*)(x1 + 4 * kq + 4);
        acc00 = fmaf(wA.x, xa0.x, fmaf(wA.y, xa0.y, fmaf(wA.z, xa0.z, fmaf(wA.w, xa0.w, acc00))));
        acc01 = fmaf(wB.x, xa1.x, fmaf(wB.y, xa1.y, fmaf(wB.z, xa1.z, fmaf(wB.w, xa1.w, acc01))));
        acc10 = fmaf(wA.x, xb0.x, fmaf(wA.y, xb0.y, fmaf(wA.z, xb0.z, fmaf(wA.w, xb0.w, acc10))));
        acc11 = fmaf(wB.x, xb1.x, fmaf(wB.y, xb1.y, fmaf(wB.z, xb1.z, fmaf(wB.w, xb1.w, acc11))));
    }
    const float bb = b_in[c0 + lane];
    float vals[2] = { acc00 + acc01 + bb, acc10 + acc11 + bb };

    float* gxs = (float*)g_xs4;
    float* gsv = (float*)g_sv4;
    #pragma unroll
    for (int rr = 0; rr < 2; ++rr) {
        const float val = vals[rr];
        const float mx = wmax(val);
        float p = __expf(val - mx);
        const float smv = wsum(p);
        p = p / smv;

        const int row = r0 + wid * 2 + rr;
        const int b = row >> 7, s = row & 127;
        const int rowo = (b * 8 + hd) * 128 + s;
        gxs[rowo * 32 + lane] = p;

        const float v  = bitonic32(p, lane);
        gsv[rowo * 33 + lane] = v;
        const float v2 = v * v, v3 = v2 * v;
        const float s1 = iscan2(v, lane);
        const float s2 = iscan2(v2, lane);
        const float s3 = iscan2(v3, lane);
        const float T1 = __shfl_sync(0xffffffffu, s1, 31);

        g_q4[rowo * 33 + lane] = make_float4(
            T1 - (s1 - v), 0.5f * (s2 - v2), -(s3 - v3) * (1.f / 6.f), (float)lane);
        if (lane == 31)
            g_q4[rowo * 33 + 32] = make_float4(0.f, 0.5f * s2, -s3 * (1.f / 6.f), 32.f);
    }
}

// ---------------------------------------------------------------------------
// K2: fused spline logits + softmax + AV. grid(8,16), 512 thr.
// Warp = row i. LANE = j (4 j per lane, lane-private sv rows -> conflict-free),
// u broadcast by shfl. Only 4 logit accumulators live.
// ---------------------------------------------------------------------------
__global__ void __launch_bounds__(512) k_spline() {
    extern __shared__ float sm_raw[];
    float4* q4   = (float4*)sm_raw;               // [128*33]
    float*  sv   = (float*)(q4 + 128 * 33);       // [128][33]
    float*  xsh  = sv + 128 * 33;                 // [128][32]
    float*  attn = xsh + 128 * 32;                // [16][128]

    const int t = threadIdx.x, lane = t & 31, wid = t >> 5;
    const int bh = blockIdx.y;

    {
        const float4* srcq = g_q4 + bh * 4224;
        for (int f = t; f < 4224; f += 512) q4[f] = srcq[f];
        const float4* srcs = g_sv4 + bh * 1056;
        for (int f = t; f < 1056; f += 512) *(float4*)(sv + 4 * f) = srcs[f];
        const float4* srcx = g_xs4 + bh * 1024;
        for (int f = t; f < 1024; f += 512) *(float4*)(xsh + 4 * f) = srcx[f];
    }
    __syncthreads();

    const int i = blockIdx.x * 16 + wid;
    const float u_own = xsh[i * 32 + lane];

    // lane-private sv row pointers (stride 33 -> distinct banks across lanes)
    const float* svj0 = sv + (0 * 32 + lane) * 33;
    const float* svj1 = sv + (1 * 32 + lane) * 33;
    const float* svj2 = sv + (2 * 32 + lane) * 33;
    const float* svj3 = sv + (3 * 32 + lane) * 33;

    float acc0 = 0.f, acc1 = 0.f, acc2 = 0.f, acc3 = 0.f;

    #pragma unroll 2
    for (int e = 0; e < 32; ++e) {
        const float u  = __shfl_sync(0xffffffffu, u_own, e);
        const float u2 = 0.5f * u * u;
        const float u3 = u * u * u * (1.f / 6.f);

        // search in 4 lane-private rows (independent chains)
        int r0 = (svj0[15] < u) ? 16 : 0;
        int r1 = (svj1[15] < u) ? 16 : 0;
        int r2 = (svj2[15] < u) ? 16 : 0;
        int r3 = (svj3[15] < u) ? 16 : 0;
        r0 += (svj0[r0 + 7] < u) ? 8 : 0;
        r1 += (svj1[r1 + 7] < u) ? 8 : 0;
        r2 += (svj2[r2 + 7] < u) ? 8 : 0;
        r3 += (svj3[r3 + 7] < u) ? 8 : 0;
        r0 += (svj0[r0 + 3] < u) ? 4 : 0;
        r1 += (svj1[r1 + 3] < u) ? 4 : 0;
        r2 += (svj2[r2 + 3] < u) ? 4 : 0;
        r3 += (svj3[r3 + 3] < u) ? 4 : 0;
        r0 += (svj0[r0 + 1] < u) ? 2 : 0;
        r1 += (svj1[r1 + 1] < u) ? 2 : 0;
        r2 += (svj2[r2 + 1] < u) ? 2 : 0;
        r3 += (svj3[r3 + 1] < u) ? 2 : 0;
        // last level: two parallel scalar loads per row
        const float a0 = svj0[r0], b0 = svj0[r0 + 1];
        const float a1 = svj1[r1], b1 = svj1[r1 + 1];
        const float a2 = svj2[r2], b2 = svj2[r2 + 1];
        const float a3 = svj3[r3], b3 = svj3[r3 + 1];
        r0 += ((a0 < u) ? 1 : 0) + ((b0 < u) ? 1 : 0);
        r1 += ((a1 < u) ? 1 : 0) + ((b1 < u) ? 1 : 0);
        r2 += ((a2 < u) ? 1 : 0) + ((b2 < u) ? 1 : 0);
        r3 += ((a3 < u) ? 1 : 0) + ((b3 < u) ? 1 : 0);

        const float4 q0 = q4[(0 * 32 + lane) * 33 + r0];
        const float4 q1 = q4[(1 * 32 + lane) * 33 + r1];
        const float4 q2 = q4[(2 * 32 + lane) * 33 + r2];
        const float4 q3 = q4[(3 * 32 + lane) * 33 + r3];
        acc0 += fmaf(u2, q0.x, fmaf(u, q0.y, fmaf(u3, q0.w, q0.z)));
        acc1 += fmaf(u2, q1.x, fmaf(u, q1.y, fmaf(u3, q1.w, q1.z)));
        acc2 += fmaf(u2, q2.x, fmaf(u, q2.y, fmaf(u3, q2.w, q2.z)));
        acc3 += fmaf(u2, q3.x, fmaf(u, q3.y, fmaf(u3, q3.w, q3.z)));
    }

    // softmax over 128 logits: lane holds j = jt*32+lane in acc_jt
    const float l0 = acc0 * (1.f / 32.f), l1 = acc1 * (1.f / 32.f);
    const float l2 = acc2 * (1.f / 32.f), l3 = acc3 * (1.f / 32.f);
    float mx = fmaxf(fmaxf(l0, l1), fmaxf(l2, l3));
    mx = wmax(mx);
    const float e0 = __expf(l0 - mx), e1 = __expf(l1 - mx);
    const float e2 = __expf(l2 - mx), e3 = __expf(l3 - mx);
    float s = (e0 + e1) + (e2 + e3);
    s = wsum(s);
    const float inv = 1.f / s;
    float* at = attn + wid * 128;
    at[0 * 32 + lane] = e0 * inv;
    at[1 * 32 + lane] = e1 * inv;
    at[2 * 32 + lane] = e2 * inv;
    at[3 * 32 + lane] = e3 * inv;
    __syncwarp();

    // out[i, e=lane] = sum_j attn[j] * x[j, e]
    float a0 = 0.f, a1 = 0.f;
    #pragma unroll 8
    for (int j = 0; j < 128; j += 2) {
        a0 = fmaf(at[j],     xsh[j * 32 + lane],       a0);
        a1 = fmaf(at[j + 1], xsh[(j + 1) * 32 + lane], a1);
    }
    ((float*)g_o4)[(bh * 128 + i) * 32 + lane] = a0 + a1;
}

// ---------------------------------------------------------------------------
// K3: out = o @ w_out^T + b_out. Same GEMM shape as K1. grid(16,8), 256 thr.
// ---------------------------------------------------------------------------
__global__ void k_out(const float* __restrict__ w_out,
                      const float* __restrict__ b_out,
                      float* __restrict__ out) {
    extern __shared__ float sm[];
    float*  xs = sm;
    float4* ws = (float4*)(sm + 16 * 256);

    const int t = threadIdx.x, lane = t & 31, wid = t >> 5;
    const int r0 = blockIdx.x * 16, c0 = blockIdx.y * 32;
    const float* go = (const float*)g_o4;

    #pragma unroll
    for (int f = t; f < 1024; f += 256) {
        const int r = f >> 6, kq = f & 63;
        const int row = r0 + r, b = row >> 7, s = row & 127;
        const int d = kq * 4, h = d >> 5, e = d & 31;
        *(float4*)(xs + r * 256 + kq * 4) =
            *(const float4*)(go + ((b * 8 + h) * 128 + s) * 32 + e);
    }
    #pragma unroll
    for (int rr = 0; rr < 4; ++rr) {
        const int cc = wid * 4 + rr;
        #pragma unroll
        for (int hh = 0; hh < 2; ++hh) {
            const int k4 = hh * 32 + lane;
            ws[cc * 65 + k4] = *(const float4*)(w_out + (c0 + cc) * 256 + k4 * 4);
        }
    }
    __syncthreads();

    const float4* wrow = ws + lane * 65;
    const float* x0 = xs + (wid * 2 + 0) * 256;
    const float* x1 = xs + (wid * 2 + 1) * 256;
    float acc00 = 0.f, acc01 = 0.f, acc10 = 0.f, acc11 = 0.f;
    #pragma unroll 8
    for (int kq = 0; kq < 64; kq += 2) {
        const float4 wA = wrow[kq], wB = wrow[kq + 1];
        const float4 xa0 = *(const float4*)(x0 + 4 * kq);
        const float4 xa1 = *(const float4*)(x0 + 4 * kq + 4);
        const float4 xb0 = *(const float4*)(x1 + 4 * kq);
        const float4 xb1 = *(const float4*)(x1 + 4 * kq + 4);
        acc00 = fmaf(wA.x, xa0.x, fmaf(wA.y, xa0.y, fmaf(wA.z, xa0.z, fmaf(wA.w, xa0.w, acc00))));
        acc01 = fmaf(wB.x, xa1.x, fmaf(wB.y, xa1.y, fmaf(wB.z, xa1.z, fmaf(wB.w, xa1.w, acc01))));
        acc10 = fmaf(wA.x, xb0.x, fmaf(wA.y, xb0.y, fmaf(wA.z, xb0.z, fmaf(wA.w, xb0.w, acc10))));
        acc11 = fmaf(wB.x, xb1.x, fmaf(wB.y, xb1.y, fmaf(wB.z, xb1.z, fmaf(wB.w, xb1.w, acc11))));
    }
    const float bb = b_out[c0 + lane];
    out[(r0 + wid * 2 + 0) * 256 + c0 + lane] = acc00 + acc01 + bb;
    out[(r0 + wid * 2 + 1) * 256 + c0 + lane] = acc10 + acc11 + bb;
}

extern "C" void kernel_launch(void* const* d_in, const int* in_sizes, int n_in,
                              void* d_out, int out_size) {
    const float* inp   = (const float*)d_in[0];
    const float* w_in  = (const float*)d_in[1];
    const float* b_in  = (const float*)d_in[2];
    const float* w_out = (const float*)d_in[3];
    const float* b_out = (const float*)d_in[4];
    float* out = (float*)d_out;
    (void)in_sizes; (void)n_in; (void)out_size;

    cudaFuncSetAttribute(k_proj,   cudaFuncAttributeMaxDynamicSharedMemorySize, SMEM_GEMM);
    cudaFuncSetAttribute(k_spline, cudaFuncAttributeMaxDynamicSharedMemorySize, SMEM_SPL);
    cudaFuncSetAttribute(k_out,    cudaFuncAttributeMaxDynamicSharedMemorySize, SMEM_GEMM);

    k_proj  <<<dim3(16, 8), 256, SMEM_GEMM>>>(inp, w_in, b_in);
    k_spline<<<dim3(8, 16), 512, SMEM_SPL>>>();
    k_out   <<<dim3(16, 8), 256, SMEM_GEMM>>>(w_out, b_out, out);
}

// round 8
// speedup vs baseline: 1.1258x; 1.1258x over previous
#include <cuda_runtime.h>

#define BH_ 16

// 16B-aligned gmem scratch
__device__ float4 g_xs4[BH_ * 1024];        // softmaxed x, stride 32 floats
__device__ float4 g_sv4[BH_ * 1152];        // sorted values, stride 36 floats
__device__ float4 g_q4 [BH_ * 128 * 33];    // rank table: (qA, qB, qC, r)
__device__ float4 g_o4 [BH_ * 1024];        // attn @ x, stride 32 floats

static const int SMEM_PROJ = (8 * 256 + 32 * 257 + 8 * 32) * 4;            // 42112
static const int SMEM_SPL  = 128 * 33 * 16 + 128 * 36 * 4
                           + 128 * 32 * 4 + 16 * 128 * 4;                  // 110592
static const int SMEM_OUT  = SMEM_PROJ;

__device__ __forceinline__ float wmax(float v) {
    #pragma unroll
    for (int o = 16; o > 0; o >>= 1) v = fmaxf(v, __shfl_xor_sync(0xffffffffu, v, o));
    return v;
}
__device__ __forceinline__ float wsum(float v) {
    #pragma unroll
    for (int o = 16; o > 0; o >>= 1) v += __shfl_xor_sync(0xffffffffu, v, o);
    return v;
}
__device__ __forceinline__ float bitonic32(float v, int l) {
    #pragma unroll
    for (int k = 2; k <= 32; k <<= 1) {
        #pragma unroll
        for (int j = k >> 1; j > 0; j >>= 1) {
            const float o = __shfl_xor_sync(0xffffffffu, v, j);
            const bool up = ((l & k) == 0);
            const bool lower = ((l & j) == 0);
            v = (lower == up) ? fminf(v, o) : fmaxf(v, o);
        }
    }
    return v;
}
__device__ __forceinline__ float iscan2(float x, int l) {
    #pragma unroll
    for (int o = 1; o < 32; o <<= 1) {
        const float n = __shfl_up_sync(0xffffffffu, x, o);
        if (l >= o) x += n;
    }
    return x;
}

// ---------------------------------------------------------------------------
// K1: in-proj GEMM (8 rows x 32 cols, K-split x2) + softmax + sort + table.
// grid(32,8), 256 thr.   [R6 version; only sv stride changed to 36]
// ---------------------------------------------------------------------------
__global__ void k_proj(const float* __restrict__ inp,
                       const float* __restrict__ w_in,
                       const float* __restrict__ b_in) {
    extern __shared__ float sm[];
    float* xs = sm;                 // [8][256]
    float* ws = sm + 8 * 256;       // [32][257]
    float* ps = ws + 32 * 257;      // [8][32]

    const int t = threadIdx.x, lane = t & 31, wid = t >> 5;
    const int r0 = blockIdx.x * 8, hd = blockIdx.y, c0 = hd * 32;

    #pragma unroll
    for (int f = t; f < 512; f += 256) {
        const int r = f >> 6, kq = f & 63;
        *(float4*)(xs + r * 256 + kq * 4) = *(const float4*)(inp + (r0 + r) * 256 + kq * 4);
    }
    #pragma unroll
    for (int rr = 0; rr < 4; ++rr) {
        const int cc = wid * 4 + rr;
        #pragma unroll
        for (int hh = 0; hh < 2; ++hh) {
            const int k4 = hh * 32 + lane;
            const float4 v = *(const float4*)(w_in + (c0 + cc) * 256 + k4 * 4);
            float* d = ws + cc * 257 + k4 * 4;
            d[0] = v.x; d[1] = v.y; d[2] = v.z; d[3] = v.w;
        }
    }
    __syncthreads();

    const int kh = wid >> 2, rg = wid & 3;
    const float* wrow = ws + lane * 257 + kh * 128;
    float acc[2] = {0.f, 0.f};
    #pragma unroll 8
    for (int kq = 0; kq < 32; ++kq) {
        const float w0 = wrow[4 * kq + 0], w1 = wrow[4 * kq + 1];
        const float w2 = wrow[4 * kq + 2], w3 = wrow[4 * kq + 3];
        #pragma unroll
        for (int rr = 0; rr < 2; ++rr) {
            const float4 x4 = *(const float4*)(xs + (rg * 2 + rr) * 256 + kh * 128 + 4 * kq);
            acc[rr] = fmaf(w0, x4.x, fmaf(w1, x4.y, fmaf(w2, x4.z, fmaf(w3, x4.w, acc[rr]))));
        }
    }
    if (kh == 1) {
        #pragma unroll
        for (int rr = 0; rr < 2; ++rr) ps[(rg * 2 + rr) * 32 + lane] = acc[rr];
    }
    __syncthreads();
    if (kh == 0) {
        const float bb = b_in[c0 + lane];
        float* gxs = (float*)g_xs4;
        float* gsv = (float*)g_sv4;
        #pragma unroll
        for (int rr = 0; rr < 2; ++rr) {
            const float val = acc[rr] + ps[(rg * 2 + rr) * 32 + lane] + bb;
            const float mx = wmax(val);
            float p = __expf(val - mx);
            const float smv = wsum(p);
            p = p / smv;

            const int row = r0 + rg * 2 + rr;
            const int b = row >> 7, s = row & 127;
            const int rowo = (b * 8 + hd) * 128 + s;
            gxs[rowo * 32 + lane] = p;

            const float v  = bitonic32(p, lane);
            gsv[rowo * 36 + lane] = v;
            const float v2 = v * v, v3 = v2 * v;
            const float s1 = iscan2(v, lane);
            const float s2 = iscan2(v2, lane);
            const float s3 = iscan2(v3, lane);
            const float T1 = __shfl_sync(0xffffffffu, s1, 31);

            g_q4[rowo * 33 + lane] = make_float4(
                T1 - (s1 - v), 0.5f * (s2 - v2), -(s3 - v3) * (1.f / 6.f), (float)lane);
            if (lane == 31)
                g_q4[rowo * 33 + 32] = make_float4(0.f, 0.5f * s2, -s3 * (1.f / 6.f), 32.f);
        }
    }
}

// ---------------------------------------------------------------------------
// K2: fused spline logits + row softmax + AV. grid(8, 16), 512 thr (16 warps).
// Warp wid owns full row i = bx*16 + wid; lane = e.  [R6 + 4-level search]
// ---------------------------------------------------------------------------
__global__ void __launch_bounds__(512) k_spline() {
    extern __shared__ float sm_raw[];
    float4* q4  = (float4*)sm_raw;                  // [128*33]
    float*  sv  = (float*)(q4 + 128 * 33);          // [128][36]
    float*  xsh = sv + 128 * 36;                    // [128][32]
    float*  attn = xsh + 128 * 32;                  // [16][128]

    const int t = threadIdx.x, lane = t & 31, wid = t >> 5;
    const int bh = blockIdx.y;

    {
        const float4* srcq = g_q4 + bh * 4224;
        for (int f = t; f < 4224; f += 512) q4[f] = srcq[f];
        const float4* srcs = g_sv4 + bh * 1152;
        for (int f = t; f < 1152; f += 512) *(float4*)(sv + 4 * f) = srcs[f];
        const float4* srcx = g_xs4 + bh * 1024;
        for (int f = t; f < 1024; f += 512) *(float4*)(xsh + 4 * f) = srcx[f];
    }
    __syncthreads();

    const int i = blockIdx.x * 16 + wid;
    const float u  = xsh[i * 32 + lane];
    const float u2 = 0.5f * u * u;
    const float u3 = u * u * u * (1.f / 6.f);

    float srow[4];
    #pragma unroll
    for (int b = 0; b < 4; ++b) {
        float cur[32];
        #pragma unroll
        for (int jj = 0; jj < 32; ++jj) {
            const int j = b * 32 + jj;
            const float* svj = sv + j * 36;
            int r = (svj[15] < u) ? 16 : 0;
            r += (svj[r + 7] < u) ? 8 : 0;
            r += (svj[r + 3] < u) ? 4 : 0;
            const float4 s4 = *(const float4*)(svj + r);   // r % 4 == 0, 16B aligned
            r += (int)(s4.x < u) + (int)(s4.y < u) + (int)(s4.z < u) + (int)(s4.w < u);
            const float4 q = q4[j * 33 + r];
            cur[jj] = fmaf(u2, q.x, fmaf(u, q.y, fmaf(u3, q.w, q.z)));
        }
        // butterfly transpose-reduce: lane l ends with sum over lanes for j=b*32+l
        #pragma unroll
        for (int o = 16; o > 0; o >>= 1) {
            #pragma unroll
            for (int k = 0; k < o; ++k) {
                const float keep = (lane & o) ? cur[k + o] : cur[k];
                const float give = (lane & o) ? cur[k] : cur[k + o];
                const float got = __shfl_xor_sync(0xffffffffu, give, o);
                cur[k] = keep + got;
            }
        }
        srow[b] = cur[0];
    }

    // softmax over the 128 distributed logits (lane holds j = b*32+lane)
    const float l0 = srow[0] * (1.f / 32.f), l1 = srow[1] * (1.f / 32.f);
    const float l2 = srow[2] * (1.f / 32.f), l3 = srow[3] * (1.f / 32.f);
    float mx = fmaxf(fmaxf(l0, l1), fmaxf(l2, l3));
    mx = wmax(mx);
    const float e0 = __expf(l0 - mx), e1 = __expf(l1 - mx);
    const float e2 = __expf(l2 - mx), e3 = __expf(l3 - mx);
    float s = (e0 + e1) + (e2 + e3);
    s = wsum(s);
    const float inv = 1.f / s;
    float* at = attn + wid * 128;
    at[0 * 32 + lane] = e0 * inv;
    at[1 * 32 + lane] = e1 * inv;
    at[2 * 32 + lane] = e2 * inv;
    at[3 * 32 + lane] = e3 * inv;
    __syncwarp();

    // out[i, e=lane] = sum_j attn[j] * x[j, e]
    float a0 = 0.f, a1 = 0.f;
    #pragma unroll 8
    for (int j = 0; j < 128; j += 2) {
        a0 = fmaf(at[j],     xsh[j * 32 + lane],       a0);
        a1 = fmaf(at[j + 1], xsh[(j + 1) * 32 + lane], a1);
    }
    ((float*)g_o4)[(bh * 128 + i) * 32 + lane] = a0 + a1;
}

// ---------------------------------------------------------------------------
// K3: out = o @ w_out^T + b_out. 8-row tiles, K-split x2. grid(32,8), 256 thr.
// [R6 version]
// ---------------------------------------------------------------------------
__global__ void k_out(const float* __restrict__ w_out,
                      const float* __restrict__ b_out,
                      float* __restrict__ out) {
    extern __shared__ float sm[];
    float* xs = sm;
    float* ws = sm + 8 * 256;
    float* ps = ws + 32 * 257;

    const int t = threadIdx.x, lane = t & 31, wid = t >> 5;
    const int r0 = blockIdx.x * 8, c0 = blockIdx.y * 32;
    const float* go = (const float*)g_o4;

    #pragma unroll
    for (int f = t; f < 512; f += 256) {
        const int r = f >> 6, kq = f & 63;
        const int row = r0 + r, b = row >> 7, s = row & 127;
        const int d = kq * 4, h = d >> 5, e = d & 31;
        *(float4*)(xs + r * 256 + kq * 4) =
            *(const float4*)(go + ((b * 8 + h) * 128 + s) * 32 + e);
    }
    #pragma unroll
    for (int rr = 0; rr < 4; ++rr) {
        const int cc = wid * 4 + rr;
        #pragma unroll
        for (int hh = 0; hh < 2; ++hh) {
            const int k4 = hh * 32 + lane;
            const float4 v = *(const float4*)(w_out + (c0 + cc) * 256 + k4 * 4);
            float* d = ws + cc * 257 + k4 * 4;
            d[0] = v.x; d[1] = v.y; d[2] = v.z; d[3] = v.w;
        }
    }
    __syncthreads();

    const int kh = wid >> 2, rg = wid & 3;
    const float* wrow = ws + lane * 257 + kh * 128;
    float acc[2] = {0.f, 0.f};
    #pragma unroll 8
    for (int kq = 0; kq < 32; ++kq) {
        const float w0 = wrow[4 * kq + 0], w1 = wrow[4 * kq + 1];
        const float w2 = wrow[4 * kq + 2], w3 = wrow[4 * kq + 3];
        #pragma unroll
        for (int rr = 0; rr < 2; ++rr) {
            const float4 x4 = *(const float4*)(xs + (rg * 2 + rr) * 256 + kh * 128 + 4 * kq);
            acc[rr] = fmaf(w0, x4.x, fmaf(w1, x4.y, fmaf(w2, x4.z, fmaf(w3, x4.w, acc[rr]))));
        }
    }
    if (kh == 1) {
        #pragma unroll
        for (int rr = 0; rr < 2; ++rr) ps[(rg * 2 + rr) * 32 + lane] = acc[rr];
    }
    __syncthreads();
    if (kh == 0) {
        const float bb = b_out[c0 + lane];
        #pragma unroll
        for (int rr = 0; rr < 2; ++rr)
            out[(r0 + rg * 2 + rr) * 256 + c0 + lane] =
                acc[rr] + ps[(rg * 2 + rr) * 32 + lane] + bb;
    }
}

extern "C" void kernel_launch(void* const* d_in, const int* in_sizes, int n_in,
                              void* d_out, int out_size) {
    const float* inp   = (const float*)d_in[0];
    const float* w_in  = (const float*)d_in[1];
    const float* b_in  = (const float*)d_in[2];
    const float* w_out = (const float*)d_in[3];
    const float* b_out = (const float*)d_in[4];
    float* out = (float*)d_out;
    (void)in_sizes; (void)n_in; (void)out_size;

    cudaFuncSetAttribute(k_proj,   cudaFuncAttributeMaxDynamicSharedMemorySize, SMEM_PROJ);
    cudaFuncSetAttribute(k_spline, cudaFuncAttributeMaxDynamicSharedMemorySize, SMEM_SPL);
    cudaFuncSetAttribute(k_out,    cudaFuncAttributeMaxDynamicSharedMemorySize, SMEM_OUT);

    k_proj  <<<dim3(32, 8), 256, SMEM_PROJ>>>(inp, w_in, b_in);
    k_spline<<<dim3(8, 16), 512, SMEM_SPL>>>();
    k_out   <<<dim3(32, 8), 256, SMEM_OUT>>>(w_out, b_out, out);
}

// round 9
// speedup vs baseline: 1.1952x; 1.0616x over previous
#include <cuda_runtime.h>

#define BH_ 16

// gmem scratch
__device__ float4 g_xs4[BH_ * 1024];          // softmaxed x, stride 32 floats
__device__ float  g_sv [BH_ * 128 * 36];      // sorted values, stride 36
__device__ float  g_qA [BH_ * 128 * 33];      // 1 - prefix1(r)      (coeff 0.5u^2)
__device__ float  g_qB [BH_ * 128 * 33];      // 0.5 * prefix2(r)    (coeff u)
__device__ float  g_qC [BH_ * 128 * 33];      // -prefix3(r)/6       (constant)
__device__ float4 g_o4 [BH_ * 1024];          // attn @ x, stride 32

static const int SMEM_PROJ = (8 * 256 + 32 * 257 + 8 * 32) * 4;            // 42112
static const int SMEM_SPL  = (3 * 128 * 33 + 128 * 36 + 128 * 32 + 8 * 128) * 4;  // 89600
static const int SMEM_OUT  = SMEM_PROJ;

__device__ __forceinline__ float wmax(float v) {
    #pragma unroll
    for (int o = 16; o > 0; o >>= 1) v = fmaxf(v, __shfl_xor_sync(0xffffffffu, v, o));
    return v;
}
__device__ __forceinline__ float wsum(float v) {
    #pragma unroll
    for (int o = 16; o > 0; o >>= 1) v += __shfl_xor_sync(0xffffffffu, v, o);
    return v;
}

// ---------------------------------------------------------------------------
// K1: in-proj GEMM (8 rows x 32 cols, K-split x2) + softmax + counting-rank
// table build (no serial sort/scan chains). grid(32,8), 256 thr.
// ---------------------------------------------------------------------------
__global__ void k_proj(const float* __restrict__ inp,
                       const float* __restrict__ w_in,
                       const float* __restrict__ b_in) {
    extern __shared__ float sm[];
    float* xs = sm;                 // [8][256]
    float* ws = sm + 8 * 256;       // [32][257]
    float* ps = ws + 32 * 257;      // [8][32]

    const int t = threadIdx.x, lane = t & 31, wid = t >> 5;
    const int r0 = blockIdx.x * 8, hd = blockIdx.y, c0 = hd * 32;

    #pragma unroll
    for (int f = t; f < 512; f += 256) {
        const int r = f >> 6, kq = f & 63;
        *(float4*)(xs + r * 256 + kq * 4) = *(const float4*)(inp + (r0 + r) * 256 + kq * 4);
    }
    #pragma unroll
    for (int rr = 0; rr < 4; ++rr) {
        const int cc = wid * 4 + rr;
        #pragma unroll
        for (int hh = 0; hh < 2; ++hh) {
            const int k4 = hh * 32 + lane;
            const float4 v = *(const float4*)(w_in + (c0 + cc) * 256 + k4 * 4);
            float* d = ws + cc * 257 + k4 * 4;
            d[0] = v.x; d[1] = v.y; d[2] = v.z; d[3] = v.w;
        }
    }
    __syncthreads();

    const int kh = wid >> 2, rg = wid & 3;
    const float* wrow = ws + lane * 257 + kh * 128;
    float acc[2] = {0.f, 0.f};
    #pragma unroll 8
    for (int kq = 0; kq < 32; ++kq) {
        const float w0 = wrow[4 * kq + 0], w1 = wrow[4 * kq + 1];
        const float w2 = wrow[4 * kq + 2], w3 = wrow[4 * kq + 3];
        #pragma unroll
        for (int rr = 0; rr < 2; ++rr) {
            const float4 x4 = *(const float4*)(xs + (rg * 2 + rr) * 256 + kh * 128 + 4 * kq);
            acc[rr] = fmaf(w0, x4.x, fmaf(w1, x4.y, fmaf(w2, x4.z, fmaf(w3, x4.w, acc[rr]))));
        }
    }
    if (kh == 1) {
        #pragma unroll
        for (int rr = 0; rr < 2; ++rr) ps[(rg * 2 + rr) * 32 + lane] = acc[rr];
    }
    __syncthreads();
    if (kh == 0) {
        const float bb = b_in[c0 + lane];
        float* gxs = (float*)g_xs4;
        #pragma unroll
        for (int rr = 0; rr < 2; ++rr) {
            const float val = acc[rr] + ps[(rg * 2 + rr) * 32 + lane] + bb;
            const float mx = wmax(val);
            float p = __expf(val - mx);
            const float smv = wsum(p);
            p = p / smv;                       // softmax row: sum == 1

            const int row = r0 + rg * 2 + rr;
            const int b = row >> 7, s = row & 127;
            const int rowo = (b * 8 + hd) * 128 + s;
            gxs[rowo * 32 + lane] = p;

            // counting rank + prefix sums below own value (no serial chains)
            const float p2o = p * p, p3o = p2o * p;
            float pre1 = 0.f, pre2 = 0.f, pre3 = 0.f;
            int rank = 0;
            #pragma unroll
            for (int f = 0; f < 32; ++f) {
                const float vf = __shfl_sync(0xffffffffu, p, f);
                const bool below = (vf < p) | ((vf == p) & (f < lane));
                if (below) {
                    const float vf2 = vf * vf;
                    pre1 += vf;
                    pre2 += vf2;
                    pre3 += vf2 * vf;
                    ++rank;
                }
            }
            g_sv[rowo * 36 + rank] = p;
            g_qA[rowo * 33 + rank] = 1.f - pre1;
            g_qB[rowo * 33 + rank] = 0.5f * pre2;
            g_qC[rowo * 33 + rank] = -pre3 * (1.f / 6.f);
            if (rank == 31) {                   // max element writes entry 32
                g_qA[rowo * 33 + 32] = 0.f;
                g_qB[rowo * 33 + 32] = 0.5f * (pre2 + p2o);
                g_qC[rowo * 33 + 32] = -(pre3 + p3o) * (1.f / 6.f);
            }
        }
    }
}

// ---------------------------------------------------------------------------
// K2: fused spline logits + row softmax + AV. grid(16,16), 256 thr (8 warps).
// Warp = row i; lane = e. Scalar tables -> conflict-free LDS.
// ---------------------------------------------------------------------------
__global__ void __launch_bounds__(256) k_spline() {
    extern __shared__ float sm_raw[];
    float* qA   = sm_raw;                     // [128*33]
    float* qB   = qA + 128 * 33;
    float* qC   = qB + 128 * 33;
    float* sv   = qC + 128 * 33;              // [128][36]
    float* xsh  = sv + 128 * 36;              // [128][32]
    float* attn = xsh + 128 * 32;             // [8][128]

    const int t = threadIdx.x, lane = t & 31, wid = t >> 5;
    const int bh = blockIdx.y;

    {
        const float4* a = (const float4*)(g_qA + bh * 4224);
        const float4* b = (const float4*)(g_qB + bh * 4224);
        const float4* c = (const float4*)(g_qC + bh * 4224);
        for (int f = t; f < 1056; f += 256) {
            *(float4*)(qA + 4 * f) = a[f];
            *(float4*)(qB + 4 * f) = b[f];
            *(float4*)(qC + 4 * f) = c[f];
        }
        const float4* sp = (const float4*)(g_sv + bh * 4608);
        for (int f = t; f < 1152; f += 256) *(float4*)(sv + 4 * f) = sp[f];
        const float4* xp = g_xs4 + bh * 1024;
        for (int f = t; f < 1024; f += 256) *(float4*)(xsh + 4 * f) = xp[f];
    }
    __syncthreads();

    const int i = blockIdx.x * 8 + wid;
    const float u  = xsh[i * 32 + lane];
    const float u2 = 0.5f * u * u;
    const float u3 = u * u * u * (1.f / 6.f);

    float srow[4];
    #pragma unroll
    for (int b = 0; b < 4; ++b) {
        float cur[32];
        #pragma unroll
        for (int jj = 0; jj < 32; ++jj) {
            const int j = b * 32 + jj;
            const float* svj = sv + j * 36;
            int r = (svj[15] < u) ? 16 : 0;
            r += (svj[r + 7] < u) ? 8 : 0;
            r += (svj[r + 3] < u) ? 4 : 0;
            r += (svj[r + 1] < u) ? 2 : 0;
            const float2 pr = *(const float2*)(svj + r);   // r even, 8B aligned
            r += (int)(pr.x < u) + (int)(pr.y < u);
            const int o = j * 33 + r;
            cur[jj] = fmaf(u2, qA[o],
                      fmaf(u,  qB[o],
                      fmaf(u3, __int2float_rn(r), qC[o])));
        }
        // butterfly transpose-reduce: lane l ends with row-sum for j = b*32+l
        #pragma unroll
        for (int o = 16; o > 0; o >>= 1) {
            #pragma unroll
            for (int k = 0; k < o; ++k) {
                const float keep = (lane & o) ? cur[k + o] : cur[k];
                const float give = (lane & o) ? cur[k] : cur[k + o];
                const float got = __shfl_xor_sync(0xffffffffu, give, o);
                cur[k] = keep + got;
            }
        }
        srow[b] = cur[0];
    }

    // softmax over 128 distributed logits (lane holds j = b*32+lane)
    const float l0 = srow[0] * (1.f / 32.f), l1 = srow[1] * (1.f / 32.f);
    const float l2 = srow[2] * (1.f / 32.f), l3 = srow[3] * (1.f / 32.f);
    float mx = fmaxf(fmaxf(l0, l1), fmaxf(l2, l3));
    mx = wmax(mx);
    const float e0 = __expf(l0 - mx), e1 = __expf(l1 - mx);
    const float e2 = __expf(l2 - mx), e3 = __expf(l3 - mx);
    float s = (e0 + e1) + (e2 + e3);
    s = wsum(s);
    const float inv = 1.f / s;
    float* at = attn + wid * 128;
    at[0 * 32 + lane] = e0 * inv;
    at[1 * 32 + lane] = e1 * inv;
    at[2 * 32 + lane] = e2 * inv;
    at[3 * 32 + lane] = e3 * inv;
    __syncwarp();

    // out[i, e=lane] = sum_j attn[j] * x[j, e]
    float a0 = 0.f, a1 = 0.f;
    #pragma unroll 8
    for (int j = 0; j < 128; j += 2) {
        a0 = fmaf(at[j],     xsh[j * 32 + lane],       a0);
        a1 = fmaf(at[j + 1], xsh[(j + 1) * 32 + lane], a1);
    }
    ((float*)g_o4)[(bh * 128 + i) * 32 + lane] = a0 + a1;
}

// ---------------------------------------------------------------------------
// K3: out = o @ w_out^T + b_out. 8-row tiles, K-split x2. grid(32,8), 256 thr.
// [unchanged from R8]
// ---------------------------------------------------------------------------
__global__ void k_out(const float* __restrict__ w_out,
                      const float* __restrict__ b_out,
                      float* __restrict__ out) {
    extern __shared__ float sm[];
    float* xs = sm;
    float* ws = sm + 8 * 256;
    float* ps = ws + 32 * 257;

    const int t = threadIdx.x, lane = t & 31, wid = t >> 5;
    const int r0 = blockIdx.x * 8, c0 = blockIdx.y * 32;
    const float* go = (const float*)g_o4;

    #pragma unroll
    for (int f = t; f < 512; f += 256) {
        const int r = f >> 6, kq = f & 63;
        const int row = r0 + r, b = row >> 7, s = row & 127;
        const int d = kq * 4, h = d >> 5, e = d & 31;
        *(float4*)(xs + r * 256 + kq * 4) =
            *(const float4*)(go + ((b * 8 + h) * 128 + s) * 32 + e);
    }
    #pragma unroll
    for (int rr = 0; rr < 4; ++rr) {
        const int cc = wid * 4 + rr;
        #pragma unroll
        for (int hh = 0; hh < 2; ++hh) {
            const int k4 = hh * 32 + lane;
            const float4 v = *(const float4*)(w_out + (c0 + cc) * 256 + k4 * 4);
            float* d = ws + cc * 257 + k4 * 4;
            d[0] = v.x; d[1] = v.y; d[2] = v.z; d[3] = v.w;
        }
    }
    __syncthreads();

    const int kh = wid >> 2, rg = wid & 3;
    const float* wrow = ws + lane * 257 + kh * 128;
    float acc[2] = {0.f, 0.f};
    #pragma unroll 8
    for (int kq = 0; kq < 32; ++kq) {
        const float w0 = wrow[4 * kq + 0], w1 = wrow[4 * kq + 1];
        const float w2 = wrow[4 * kq + 2], w3 = wrow[4 * kq + 3];
        #pragma unroll
        for (int rr = 0; rr < 2; ++rr) {
            const float4 x4 = *(const float4*)(xs + (rg * 2 + rr) * 256 + kh * 128 + 4 * kq);
            acc[rr] = fmaf(w0, x4.x, fmaf(w1, x4.y, fmaf(w2, x4.z, fmaf(w3, x4.w, acc[rr]))));
        }
    }
    if (kh == 1) {
        #pragma unroll
        for (int rr = 0; rr < 2; ++rr) ps[(rg * 2 + rr) * 32 + lane] = acc[rr];
    }
    __syncthreads();
    if (kh == 0) {
        const float bb = b_out[c0 + lane];
        #pragma unroll
        for (int rr = 0; rr < 2; ++rr)
            out[(r0 + rg * 2 + rr) * 256 + c0 + lane] =
                acc[rr] + ps[(rg * 2 + rr) * 32 + lane] + bb;
    }
}

extern "C" void kernel_launch(void* const* d_in, const int* in_sizes, int n_in,
                              void* d_out, int out_size) {
    const float* inp   = (const float*)d_in[0];
    const float* w_in  = (const float*)d_in[1];
    const float* b_in  = (const float*)d_in[2];
    const float* w_out = (const float*)d_in[3];
    const float* b_out = (const float*)d_in[4];
    float* out = (float*)d_out;
    (void)in_sizes; (void)n_in; (void)out_size;

    cudaFuncSetAttribute(k_proj,   cudaFuncAttributeMaxDynamicSharedMemorySize, SMEM_PROJ);
    cudaFuncSetAttribute(k_spline, cudaFuncAttributeMaxDynamicSharedMemorySize, SMEM_SPL);
    cudaFuncSetAttribute(k_out,    cudaFuncAttributeMaxDynamicSharedMemorySize, SMEM_OUT);

    k_proj  <<<dim3(32, 8),  256, SMEM_PROJ>>>(inp, w_in, b_in);
    k_spline<<<dim3(16, 16), 256, SMEM_SPL>>>();
    k_out   <<<dim3(32, 8),  256, SMEM_OUT>>>(w_out, b_out, out);
}

// round 10
// speedup vs baseline: 1.2645x; 1.0580x over previous
#include <cuda_runtime.h>

#define BH_ 16

// gmem scratch
__device__ float4 g_xs4[BH_ * 1024];          // softmaxed x, stride 32 floats
__device__ float  g_sv [BH_ * 128 * 36];      // sorted values, stride 36
__device__ float  g_qA [BH_ * 128 * 33];      // 1 - prefix1(r)     (coeff 0.5u^2)
__device__ float  g_qB [BH_ * 128 * 33];      // 0.5 * prefix2(r)   (coeff u)
__device__ float  g_qC [BH_ * 128 * 33];      // -prefix3(r)/6      (constant)

static const int SMEM_PROJ = (8 * 256 + 32 * 257 + 8 * 32) * 4;            // 42112
static const int SMEM_SPL  = (3 * 128 * 33 + 128 * 36 + 128 * 32
                              + 8 * 128 + 8 * 32) * 4;                     // 90624

__device__ __forceinline__ float wmax(float v) {
    #pragma unroll
    for (int o = 16; o > 0; o >>= 1) v = fmaxf(v, __shfl_xor_sync(0xffffffffu, v, o));
    return v;
}
__device__ __forceinline__ float wsum(float v) {
    #pragma unroll
    for (int o = 16; o > 0; o >>= 1) v += __shfl_xor_sync(0xffffffffu, v, o);
    return v;
}

// ---------------------------------------------------------------------------
// K1: in-proj GEMM + softmax + counting-rank tables + out := b_out (bias init).
// grid(32,8), 256 thr.
// ---------------------------------------------------------------------------
__global__ void k_proj(const float* __restrict__ inp,
                       const float* __restrict__ w_in,
                       const float* __restrict__ b_in,
                       const float* __restrict__ b_out,
                       float* __restrict__ out) {
    extern __shared__ float sm[];
    float* xs = sm;                 // [8][256]
    float* ws = sm + 8 * 256;       // [32][257]
    float* ps = ws + 32 * 257;      // [8][32]

    const int t = threadIdx.x, lane = t & 31, wid = t >> 5;
    const int r0 = blockIdx.x * 8, hd = blockIdx.y, c0 = hd * 32;

    // bias-init of out: 256 blocks x 256 thr covers 65536 elements exactly once
    {
        const int idx = ((blockIdx.y * 32 + blockIdx.x) << 8) + t;
        out[idx] = b_out[idx & 255];
    }

    #pragma unroll
    for (int f = t; f < 512; f += 256) {
        const int r = f >> 6, kq = f & 63;
        *(float4*)(xs + r * 256 + kq * 4) = *(const float4*)(inp + (r0 + r) * 256 + kq * 4);
    }
    #pragma unroll
    for (int rr = 0; rr < 4; ++rr) {
        const int cc = wid * 4 + rr;
        #pragma unroll
        for (int hh = 0; hh < 2; ++hh) {
            const int k4 = hh * 32 + lane;
            const float4 v = *(const float4*)(w_in + (c0 + cc) * 256 + k4 * 4);
            float* d = ws + cc * 257 + k4 * 4;
            d[0] = v.x; d[1] = v.y; d[2] = v.z; d[3] = v.w;
        }
    }
    __syncthreads();

    const int kh = wid >> 2, rg = wid & 3;
    const float* wrow = ws + lane * 257 + kh * 128;
    float acc[2] = {0.f, 0.f};
    #pragma unroll 8
    for (int kq = 0; kq < 32; ++kq) {
        const float w0 = wrow[4 * kq + 0], w1 = wrow[4 * kq + 1];
        const float w2 = wrow[4 * kq + 2], w3 = wrow[4 * kq + 3];
        #pragma unroll
        for (int rr = 0; rr < 2; ++rr) {
            const float4 x4 = *(const float4*)(xs + (rg * 2 + rr) * 256 + kh * 128 + 4 * kq);
            acc[rr] = fmaf(w0, x4.x, fmaf(w1, x4.y, fmaf(w2, x4.z, fmaf(w3, x4.w, acc[rr]))));
        }
    }
    if (kh == 1) {
        #pragma unroll
        for (int rr = 0; rr < 2; ++rr) ps[(rg * 2 + rr) * 32 + lane] = acc[rr];
    }
    __syncthreads();
    if (kh == 0) {
        const float bb = b_in[c0 + lane];
        float* gxs = (float*)g_xs4;
        #pragma unroll
        for (int rr = 0; rr < 2; ++rr) {
            const float val = acc[rr] + ps[(rg * 2 + rr) * 32 + lane] + bb;
            const float mx = wmax(val);
            float p = __expf(val - mx);
            const float smv = wsum(p);
            p = p / smv;                       // softmax row: sum == 1

            const int row = r0 + rg * 2 + rr;
            const int b = row >> 7, s = row & 127;
            const int rowo = (b * 8 + hd) * 128 + s;
            gxs[rowo * 32 + lane] = p;

            // counting rank + prefix sums below own value (no serial chains)
            const float p2o = p * p, p3o = p2o * p;
            float pre1 = 0.f, pre2 = 0.f, pre3 = 0.f;
            int rank = 0;
            #pragma unroll
            for (int f = 0; f < 32; ++f) {
                const float vf = __shfl_sync(0xffffffffu, p, f);
                const bool below = (vf < p) | ((vf == p) & (f < lane));
                if (below) {
                    const float vf2 = vf * vf;
                    pre1 += vf;
                    pre2 += vf2;
                    pre3 += vf2 * vf;
                    ++rank;
                }
            }
            g_sv[rowo * 36 + rank] = p;
            g_qA[rowo * 33 + rank] = 1.f - pre1;
            g_qB[rowo * 33 + rank] = 0.5f * pre2;
            g_qC[rowo * 33 + rank] = -pre3 * (1.f / 6.f);
            if (rank == 31) {
                g_qA[rowo * 33 + 32] = 0.f;
                g_qB[rowo * 33 + 32] = 0.5f * (pre2 + p2o);
                g_qC[rowo * 33 + 32] = -(pre3 + p3o) * (1.f / 6.f);
            }
        }
    }
}

// ---------------------------------------------------------------------------
// K2: spline logits + row softmax + AV + partial out-projection (atomic add).
// grid(16,16), 256 thr (8 warps). Warp = row i; lane = e.
// ---------------------------------------------------------------------------
__global__ void __launch_bounds__(256) k_spline(const float* __restrict__ w_out,
                                                float* __restrict__ out) {
    extern __shared__ float sm_raw[];
    float* qA   = sm_raw;                     // [128*33]  (reused as wsm later)
    float* qB   = qA + 128 * 33;
    float* qC   = qB + 128 * 33;
    float* sv   = qC + 128 * 33;              // [128][36]
    float* xsh  = sv + 128 * 36;              // [128][32]
    float* attn = xsh + 128 * 32;             // [8][128]
    float* osm  = attn + 8 * 128;             // [8][32]

    const int t = threadIdx.x, lane = t & 31, wid = t >> 5;
    const int bh = blockIdx.y;
    const int bq = bh >> 3, hq = bh & 7;

    {
        const float4* a = (const float4*)(g_qA + bh * 4224);
        const float4* b = (const float4*)(g_qB + bh * 4224);
        const float4* c = (const float4*)(g_qC + bh * 4224);
        for (int f = t; f < 1056; f += 256) {
            *(float4*)(qA + 4 * f) = a[f];
            *(float4*)(qB + 4 * f) = b[f];
            *(float4*)(qC + 4 * f) = c[f];
        }
        const float4* sp = (const float4*)(g_sv + bh * 4608);
        for (int f = t; f < 1152; f += 256) *(float4*)(sv + 4 * f) = sp[f];
        const float4* xp = g_xs4 + bh * 1024;
        for (int f = t; f < 1024; f += 256) *(float4*)(xsh + 4 * f) = xp[f];
    }
    __syncthreads();

    const int i = blockIdx.x * 8 + wid;
    const float u  = xsh[i * 32 + lane];
    const float u2 = 0.5f * u * u;
    const float u3 = u * u * u * (1.f / 6.f);

    float srow[4];
    #pragma unroll
    for (int b = 0; b < 4; ++b) {
        float cur[32];
        #pragma unroll
        for (int jj = 0; jj < 32; ++jj) {
            const int j = b * 32 + jj;
            const float* svj = sv + j * 36;
            int r = (svj[15] < u) ? 16 : 0;
            r += (svj[r + 7] < u) ? 8 : 0;
            r += (svj[r + 3] < u) ? 4 : 0;
            r += (svj[r + 1] < u) ? 2 : 0;
            const float2 pr = *(const float2*)(svj + r);
            r += (int)(pr.x < u) + (int)(pr.y < u);
            const int o = j * 33 + r;
            cur[jj] = fmaf(u2, qA[o],
                      fmaf(u,  qB[o],
                      fmaf(u3, __int2float_rn(r), qC[o])));
        }
        #pragma unroll
        for (int o = 16; o > 0; o >>= 1) {
            #pragma unroll
            for (int k = 0; k < o; ++k) {
                const float keep = (lane & o) ? cur[k + o] : cur[k];
                const float give = (lane & o) ? cur[k] : cur[k + o];
                const float got = __shfl_xor_sync(0xffffffffu, give, o);
                cur[k] = keep + got;
            }
        }
        srow[b] = cur[0];
    }

    const float l0 = srow[0] * (1.f / 32.f), l1 = srow[1] * (1.f / 32.f);
    const float l2 = srow[2] * (1.f / 32.f), l3 = srow[3] * (1.f / 32.f);
    float mx = fmaxf(fmaxf(l0, l1), fmaxf(l2, l3));
    mx = wmax(mx);
    const float e0 = __expf(l0 - mx), e1 = __expf(l1 - mx);
    const float e2 = __expf(l2 - mx), e3 = __expf(l3 - mx);
    float s = (e0 + e1) + (e2 + e3);
    s = wsum(s);
    const float inv = 1.f / s;
    float* at = attn + wid * 128;
    at[0 * 32 + lane] = e0 * inv;
    at[1 * 32 + lane] = e1 * inv;
    at[2 * 32 + lane] = e2 * inv;
    at[3 * 32 + lane] = e3 * inv;
    __syncwarp();

    // o[i, e=lane] = sum_j attn[j] * x[j, e]
    float a0 = 0.f, a1 = 0.f;
    #pragma unroll 8
    for (int j = 0; j < 128; j += 2) {
        a0 = fmaf(at[j],     xsh[j * 32 + lane],       a0);
        a1 = fmaf(at[j + 1], xsh[(j + 1) * 32 + lane], a1);
    }
    osm[wid * 32 + lane] = a0 + a1;
    __syncthreads();   // osm ready; all spline reads of qA/qB/qC done

    // ---- partial out-projection: out[row, e] += sum_f o[row][f] * w_out[e][h*32+f]
    // stage w_out slice coalesced into (dead) qA region, stride 33 (conflict-free)
    float* wsm = qA;   // needs 256*33 = 8448 floats <= 12672
    for (int g = t; g < 8192; g += 256) {
        const int e = g >> 5, f = g & 31;
        wsm[e * 33 + f] = w_out[(e << 8) + (hq << 5) + f];
    }
    __syncthreads();

    {
        const int e = t;
        float wreg[32];
        #pragma unroll
        for (int f = 0; f < 32; ++f) wreg[f] = wsm[e * 33 + f];

        #pragma unroll
        for (int r = 0; r < 8; ++r) {
            const float4* ob = (const float4*)(osm + r * 32);
            float acc = 0.f;
            #pragma unroll
            for (int k = 0; k < 8; ++k) {
                const float4 o4 = ob[k];     // broadcast LDS.128
                acc = fmaf(o4.x, wreg[4 * k + 0],
                      fmaf(o4.y, wreg[4 * k + 1],
                      fmaf(o4.z, wreg[4 * k + 2],
                      fmaf(o4.w, wreg[4 * k + 3], acc))));
            }
            const int row = (bq << 7) + blockIdx.x * 8 + r;
            atomicAdd(out + row * 256 + e, acc);
        }
    }
}

extern "C" void kernel_launch(void* const* d_in, const int* in_sizes, int n_in,
                              void* d_out, int out_size) {
    const float* inp   = (const float*)d_in[0];
    const float* w_in  = (const float*)d_in[1];
    const float* b_in  = (const float*)d_in[2];
    const float* w_out = (const float*)d_in[3];
    const float* b_out = (const float*)d_in[4];
    float* out = (float*)d_out;
    (void)in_sizes; (void)n_in; (void)out_size;

    cudaFuncSetAttribute(k_proj,   cudaFuncAttributeMaxDynamicSharedMemorySize, SMEM_PROJ);
    cudaFuncSetAttribute(k_spline, cudaFuncAttributeMaxDynamicSharedMemorySize, SMEM_SPL);

    k_proj  <<<dim3(32, 8),  256, SMEM_PROJ>>>(inp, w_in, b_in, b_out, out);
    k_spline<<<dim3(16, 16), 256, SMEM_SPL>>>(w_out, out);
}